// round 1
// baseline (speedup 1.0000x reference)
#include <cuda_runtime.h>
#include <math.h>

// ---------------- problem constants ----------------
#define BB     16
#define LCTX   512
#define KVAR   16
#define HPRED  96
#define DM     512
#define NST    16
#define NLAY   3
#define DFF    2048
#define PATCH  16
#define STRIDEP 8
#define PP     63            // (512-16)/8+1
#define DIN    1024          // 2*DM
#define RNK    32            // DT_RANK
#define SEQ    (KVAR*PP)     // 1008 tokens per batch
#define TT     (BB*SEQ)      // 16128 total tokens
#define EPSF   1e-5f
#define HWLD   (PP*DM)       // 32256 head_w row length

// ---------------- scratch (device globals; padded for scan prefetch) ----
__device__ float g_mean[BB*KVAR];
__device__ float g_std[BB*KVAR];
__device__ float g_z   [TT*DM];
__device__ float g_tmp [TT*DM];
__device__ float g_hln [TT*DM];
__device__ float g_u   [TT*DIN + DIN];
__device__ float g_zg  [TT*DIN + DIN];
__device__ float g_xdbl[TT*64 + 64];
__device__ float g_delta[TT*DIN + DIN];
__device__ float g_y2  [TT*DIN];
__device__ float g_hff [TT*DFF];
__device__ float g_headp[PP*BB*KVAR*HPRED];

// ---------------- helpers ----------------
__device__ __forceinline__ float siluf(float x){ return x / (1.f + __expf(-x)); }
__device__ __forceinline__ float softplusf(float x){
    return fmaxf(x, 0.f) + log1pf(expf(-fabsf(x)));
}
__device__ __forceinline__ float geluf(float x){
    return 0.5f * x * (1.f + erff(x * 0.70710678118654752f));
}

// ---------------- per-(b,k) mean/std over L ----------------
__global__ void stats_kernel(const float* __restrict__ x){
    int bk = blockIdx.x; int b = bk >> 4, k = bk & 15;
    int tid = threadIdx.x;
    float s = 0.f, q = 0.f;
    for (int l = tid; l < LCTX; l += 256){
        float v = x[(b*LCTX + l)*KVAR + k];
        s += v; q += v*v;
    }
    __shared__ float sh[64];
#pragma unroll
    for (int o = 16; o; o >>= 1){
        s += __shfl_xor_sync(~0u, s, o);
        q += __shfl_xor_sync(~0u, q, o);
    }
    int w = tid >> 5;
    if ((tid & 31) == 0){ sh[w] = s; sh[w+32] = q; }
    __syncthreads();
    if (tid == 0){
        float S = 0.f, Q = 0.f;
        for (int i = 0; i < 8; i++){ S += sh[i]; Q += sh[32+i]; }
        float mu  = S * (1.f/LCTX);
        float var = Q * (1.f/LCTX) - mu*mu;
        g_mean[bk] = mu;
        g_std[bk]  = sqrtf(var + EPSF);
    }
}

// ---------------- patch embedding + pos + var embed ----------------
__global__ void embed_kernel(const float* __restrict__ x,
                             const float* __restrict__ pw,
                             const float* __restrict__ pb,
                             const float* __restrict__ pos,
                             const float* __restrict__ vemb){
    int row = blockIdx.x;                    // token row in [0,TT)
    int b = row / SEQ, rem = row % SEQ;
    int p = rem >> 4, k = rem & 15;
    int bk = b*KVAR + k;
    __shared__ float xs[PATCH];
    int tid = threadIdx.x;                   // 128
    if (tid < PATCH){
        float v = x[(b*LCTX + p*STRIDEP + tid)*KVAR + k];
        xs[tid] = (v - g_mean[bk]) / g_std[bk];
    }
    __syncthreads();
#pragma unroll
    for (int j = 0; j < 4; j++){
        int d = tid + j*128;
        float acc = pb[d] + pos[p*DM + d] + vemb[k*DM + d];
        const float4* w4 = (const float4*)(pw + d*PATCH);
#pragma unroll
        for (int t4 = 0; t4 < 4; t4++){
            float4 w = w4[t4];
            acc += xs[t4*4+0]*w.x + xs[t4*4+1]*w.y + xs[t4*4+2]*w.z + xs[t4*4+3]*w.w;
        }
        g_z[row*DM + d] = acc;
    }
}

// ---------------- generic NT GEMM: C[M,N] = A[M,K] * W[N,K]^T ----------
enum { EP_NONE=0, EP_SPLIT=1, EP_SOFTPLUS=2, EP_GELU=3, EP_BIAS_RES=4, EP_RES=5 };

template<int EP>
__global__ void gemm_nt(const float* __restrict__ A, int lda,
                        const float* __restrict__ W, int Kd,
                        float* __restrict__ out0, float* __restrict__ out1, int ldo,
                        const float* __restrict__ bias, const float* __restrict__ res){
    __shared__ float As[16][64];
    __shared__ float Ws[16][64];
    int tid = threadIdx.x;                   // 256
    int nt = blockIdx.x, mt = blockIdx.y;
    int lm = tid >> 2;
    int lk = (tid & 3) * 4;
    const float* Ag = A + (size_t)(mt*64 + lm)*lda + lk;
    const float* Wg = W + (size_t)(nt*64 + lm)*Kd  + lk;
    int tx = tid & 15, ty = tid >> 4;
    float acc[4][4];
#pragma unroll
    for (int i = 0; i < 4; i++)
#pragma unroll
        for (int j = 0; j < 4; j++) acc[i][j] = 0.f;

    for (int kt = 0; kt < Kd; kt += 16){
        float4 av = *(const float4*)(Ag + kt);
        float4 wv = *(const float4*)(Wg + kt);
        As[lk+0][lm]=av.x; As[lk+1][lm]=av.y; As[lk+2][lm]=av.z; As[lk+3][lm]=av.w;
        Ws[lk+0][lm]=wv.x; Ws[lk+1][lm]=wv.y; Ws[lk+2][lm]=wv.z; Ws[lk+3][lm]=wv.w;
        __syncthreads();
#pragma unroll
        for (int k = 0; k < 16; k++){
            float4 a = *(const float4*)&As[k][ty*4];
            float4 w = *(const float4*)&Ws[k][tx*4];
            acc[0][0]+=a.x*w.x; acc[0][1]+=a.x*w.y; acc[0][2]+=a.x*w.z; acc[0][3]+=a.x*w.w;
            acc[1][0]+=a.y*w.x; acc[1][1]+=a.y*w.y; acc[1][2]+=a.y*w.z; acc[1][3]+=a.y*w.w;
            acc[2][0]+=a.z*w.x; acc[2][1]+=a.z*w.y; acc[2][2]+=a.z*w.z; acc[2][3]+=a.z*w.w;
            acc[3][0]+=a.w*w.x; acc[3][1]+=a.w*w.y; acc[3][2]+=a.w*w.z; acc[3][3]+=a.w*w.w;
        }
        __syncthreads();
    }

#pragma unroll
    for (int i = 0; i < 4; i++){
        int row = mt*64 + ty*4 + i;
#pragma unroll
        for (int j = 0; j < 4; j++){
            int col = nt*64 + tx*4 + j;
            float v = acc[i][j];
            if (EP == EP_NONE){
                out0[(size_t)row*ldo + col] = v;
            } else if (EP == EP_SPLIT){
                if (col < DIN) out0[(size_t)row*DIN + col] = siluf(v);
                else           out1[(size_t)row*DIN + col - DIN] = v;
            } else if (EP == EP_SOFTPLUS){
                out0[(size_t)row*ldo + col] = softplusf(v + bias[col]);
            } else if (EP == EP_GELU){
                out0[(size_t)row*ldo + col] = geluf(v + bias[col]);
            } else if (EP == EP_BIAS_RES){
                out0[(size_t)row*ldo + col] = v + bias[col] + res[(size_t)row*ldo + col];
            } else { // EP_RES
                out0[(size_t)row*ldo + col] = v + res[(size_t)row*ldo + col];
            }
        }
    }
}

// ---------------- layer norm (warp per row of 512); optional 2nd LN ----
template<bool DOUBLE>
__global__ void ln_kernel(const float* __restrict__ in,
                          const float* __restrict__ g1, const float* __restrict__ b1,
                          float* __restrict__ o1,
                          const float* __restrict__ g2, const float* __restrict__ b2,
                          float* __restrict__ o2){
    int w = threadIdx.x >> 5, lane = threadIdx.x & 31;
    int row = blockIdx.x*8 + w;
    const float4* in4 = (const float4*)(in + (size_t)row*DM);
    float4 v[4];
    float s = 0.f, q = 0.f;
#pragma unroll
    for (int i = 0; i < 4; i++){
        v[i] = in4[lane + 32*i];
        s += v[i].x + v[i].y + v[i].z + v[i].w;
        q += v[i].x*v[i].x + v[i].y*v[i].y + v[i].z*v[i].z + v[i].w*v[i].w;
    }
#pragma unroll
    for (int o = 16; o; o >>= 1){
        s += __shfl_xor_sync(~0u, s, o);
        q += __shfl_xor_sync(~0u, q, o);
    }
    float mu = s * (1.f/DM);
    float rs = rsqrtf(q*(1.f/DM) - mu*mu + EPSF);
    float4 zz[4];
    float s2 = 0.f, q2 = 0.f;
#pragma unroll
    for (int i = 0; i < 4; i++){
        float4 gg = ((const float4*)g1)[lane + 32*i];
        float4 bb = ((const float4*)b1)[lane + 32*i];
        zz[i].x = (v[i].x - mu)*rs*gg.x + bb.x;
        zz[i].y = (v[i].y - mu)*rs*gg.y + bb.y;
        zz[i].z = (v[i].z - mu)*rs*gg.z + bb.z;
        zz[i].w = (v[i].w - mu)*rs*gg.w + bb.w;
        if (DOUBLE){
            s2 += zz[i].x + zz[i].y + zz[i].z + zz[i].w;
            q2 += zz[i].x*zz[i].x + zz[i].y*zz[i].y + zz[i].z*zz[i].z + zz[i].w*zz[i].w;
        }
        ((float4*)(o1 + (size_t)row*DM))[lane + 32*i] = zz[i];
    }
    if (DOUBLE){
#pragma unroll
        for (int o = 16; o; o >>= 1){
            s2 += __shfl_xor_sync(~0u, s2, o);
            q2 += __shfl_xor_sync(~0u, q2, o);
        }
        float mu2 = s2 * (1.f/DM);
        float rs2 = rsqrtf(q2*(1.f/DM) - mu2*mu2 + EPSF);
#pragma unroll
        for (int i = 0; i < 4; i++){
            float4 gg = ((const float4*)g2)[lane + 32*i];
            float4 bb = ((const float4*)b2)[lane + 32*i];
            float4 o4;
            o4.x = (zz[i].x - mu2)*rs2*gg.x + bb.x;
            o4.y = (zz[i].y - mu2)*rs2*gg.y + bb.y;
            o4.z = (zz[i].z - mu2)*rs2*gg.z + bb.z;
            o4.w = (zz[i].w - mu2)*rs2*gg.w + bb.w;
            ((float4*)(o2 + (size_t)row*DM))[lane + 32*i] = o4;
        }
    }
}

// ---------------- selective scan ----------------
// One (b,d) chain split across 2 adjacent lanes (8 states each).
// Fast path (A arithmetic progression per lane): 2 exp/step; general: 8 exp/step.
__global__ void scan_kernel(const float* __restrict__ delta,
                            const float* __restrict__ u,
                            const float* __restrict__ zg,
                            const float* __restrict__ xdbl,
                            const float* __restrict__ A_log,
                            const float* __restrict__ Dp,
                            float* __restrict__ y2){
    int blk = blockIdx.x;                    // 128 blocks
    int b = blk >> 3, dblk = blk & 7;
    int t = threadIdx.x;                     // 256
    int half = t & 1;
    int d = dblk*128 + (t >> 1);
    int nb = half * 8;

    float Aa[8];
#pragma unroll
    for (int j = 0; j < 8; j++) Aa[j] = -expf(A_log[d*NST + nb + j]);
    float A0 = Aa[0];
    float stepA = Aa[1] - Aa[0];
    bool prog = true;
#pragma unroll
    for (int j = 0; j < 8; j++){
        float e = A0 + (float)j * stepA;
        if (fabsf(Aa[j] - e) > 1e-5f*fabsf(e) + 1e-7f) prog = false;
    }
    float Dd = Dp[d];

    float h[8];
#pragma unroll
    for (int j = 0; j < 8; j++) h[j] = 0.f;

    size_t base = (size_t)(b*SEQ)*DIN + d;
    const float* xb = xdbl + (size_t)(b*SEQ)*64 + 32 + nb;

    // prefetch step 0
    float dv = delta[base], uv = u[base], zv = zg[base];
    float4 B0 = *(const float4*)(xb);
    float4 B1 = *(const float4*)(xb + 4);
    float4 C0 = *(const float4*)(xb + 16);
    float4 C1 = *(const float4*)(xb + 20);

    for (int s = 0; s < SEQ; s++){
        // issue next-step loads early (buffers are padded by one row)
        size_t baseN = base + DIN;
        const float* xbN = xb + 64;
        float dvN = delta[baseN], uvN = u[baseN], zvN = zg[baseN];
        float4 B0N = *(const float4*)(xbN);
        float4 B1N = *(const float4*)(xbN + 4);
        float4 C0N = *(const float4*)(xbN + 16);
        float4 C1N = *(const float4*)(xbN + 20);

        float du = dv * uv;
        float y = 0.f;
        if (prog){
            float e = __expf(dv * A0);
            float r = __expf(dv * stepA);
            h[0] = h[0]*e + du*B0.x; y += h[0]*C0.x; e *= r;
            h[1] = h[1]*e + du*B0.y; y += h[1]*C0.y; e *= r;
            h[2] = h[2]*e + du*B0.z; y += h[2]*C0.z; e *= r;
            h[3] = h[3]*e + du*B0.w; y += h[3]*C0.w; e *= r;
            h[4] = h[4]*e + du*B1.x; y += h[4]*C1.x; e *= r;
            h[5] = h[5]*e + du*B1.y; y += h[5]*C1.y; e *= r;
            h[6] = h[6]*e + du*B1.z; y += h[6]*C1.z; e *= r;
            h[7] = h[7]*e + du*B1.w; y += h[7]*C1.w;
        } else {
            float Bv[8] = {B0.x,B0.y,B0.z,B0.w,B1.x,B1.y,B1.z,B1.w};
            float Cv[8] = {C0.x,C0.y,C0.z,C0.w,C1.x,C1.y,C1.z,C1.w};
#pragma unroll
            for (int j = 0; j < 8; j++){
                float e = __expf(dv * Aa[j]);
                h[j] = h[j]*e + du*Bv[j];
                y += h[j]*Cv[j];
            }
        }
        float ysum = y + __shfl_xor_sync(~0u, y, 1);
        if (!half){
            float out = (ysum + uv*Dd) * siluf(zv);
            y2[base] = out;
        }
        base = baseN; xb = xbN;
        dv = dvN; uv = uvN; zv = zvN;
        B0 = B0N; B1 = B1N; C0 = C0N; C1 = C1N;
    }
}

// ---------------- head: partial GEMM per patch index p ----------------
// C[(b,k), hh] += sum_d zf[b*SEQ + p*K + k, d] * head_w[hh, p*DM + d]
__global__ void head_partial(const float* __restrict__ zf, const float* __restrict__ hw){
    int p = blockIdx.x, mt = blockIdx.y;     // p in [0,63), mt in [0,4)
    __shared__ float As[16][64];
    __shared__ float Ws[16][96];
    int tid = threadIdx.x;                   // 256
    int lm = tid >> 2, lk = (tid & 3) * 4;
    int bkrow = mt*64 + lm;
    int b = bkrow >> 4, kk = bkrow & 15;
    const float* Ag = zf + (size_t)(b*SEQ + p*KVAR + kk)*DM + lk;
    int tx = tid & 15, ty = tid >> 4;
    float acc[4][6];
#pragma unroll
    for (int i = 0; i < 4; i++)
#pragma unroll
        for (int j = 0; j < 6; j++) acc[i][j] = 0.f;

    for (int kt = 0; kt < DM; kt += 16){
        float4 av = *(const float4*)(Ag + kt);
        As[lk+0][lm]=av.x; As[lk+1][lm]=av.y; As[lk+2][lm]=av.z; As[lk+3][lm]=av.w;
#pragma unroll
        for (int i = 0; i < 6; i++){
            int e = tid + i*256;             // 1536 = 96*16 elements
            int n = e >> 4, kq = e & 15;
            Ws[kq][n] = hw[(size_t)n*HWLD + p*DM + kt + kq];
        }
        __syncthreads();
#pragma unroll
        for (int k = 0; k < 16; k++){
            float4 a = *(const float4*)&As[k][ty*4];
            float av4[4] = {a.x, a.y, a.z, a.w};
#pragma unroll
            for (int j = 0; j < 6; j++){
                float wv = Ws[k][tx*6 + j];
#pragma unroll
                for (int i = 0; i < 4; i++) acc[i][j] += av4[i]*wv;
            }
        }
        __syncthreads();
    }
#pragma unroll
    for (int i = 0; i < 4; i++)
#pragma unroll
        for (int j = 0; j < 6; j++)
            g_headp[(size_t)(p*256 + mt*64 + ty*4 + i)*HPRED + tx*6 + j] = acc[i][j];
}

// ---------------- head reduction + de-normalization ----------------
__global__ void head_final(const float* __restrict__ hb, float* __restrict__ out){
    int idx = blockIdx.x*256 + threadIdx.x;  // 24576 = 256*96
    int bk = idx / HPRED, hh = idx % HPRED;
    float s = 0.f;
    for (int p = 0; p < PP; p++) s += g_headp[(size_t)p*(BB*KVAR*HPRED) + idx];
    s += hb[hh];
    int b = bk >> 4, k = bk & 15;
    out[b*(HPRED*KVAR) + hh*KVAR + k] = s * g_std[bk] + g_mean[bk];
}

// ---------------- launch ----------------
extern "C" void kernel_launch(void* const* d_in, const int* in_sizes, int n_in,
                              void* d_out, int out_size){
    const float* x        = (const float*)d_in[0];
    const float* patch_w  = (const float*)d_in[1];
    const float* patch_b  = (const float*)d_in[2];
    const float* pos      = (const float*)d_in[3];
    const float* vemb     = (const float*)d_in[4];
    const float* in_w     = (const float*)d_in[5];
    const float* xp_w     = (const float*)d_in[6];
    const float* dt_w     = (const float*)d_in[7];
    const float* dt_b     = (const float*)d_in[8];
    const float* A_log    = (const float*)d_in[9];
    const float* D_par    = (const float*)d_in[10];
    const float* out_w    = (const float*)d_in[11];
    const float* tmb_g    = (const float*)d_in[12];
    const float* tmb_b    = (const float*)d_in[13];
    const float* ffn_g    = (const float*)d_in[14];
    const float* ffn_b    = (const float*)d_in[15];
    const float* ffn_w1   = (const float*)d_in[16];
    const float* ffn_b1   = (const float*)d_in[17];
    const float* ffn_w2   = (const float*)d_in[18];
    const float* ffn_b2   = (const float*)d_in[19];
    const float* norm_g   = (const float*)d_in[20];
    const float* norm_b   = (const float*)d_in[21];
    const float* head_w   = (const float*)d_in[22];
    const float* head_b   = (const float*)d_in[23];
    float* out = (float*)d_out;

    float *z, *tmp, *hln, *u, *zgp, *xdbl, *delta, *y2, *hff;
    cudaGetSymbolAddress((void**)&z,    g_z);
    cudaGetSymbolAddress((void**)&tmp,  g_tmp);
    cudaGetSymbolAddress((void**)&hln,  g_hln);
    cudaGetSymbolAddress((void**)&u,    g_u);
    cudaGetSymbolAddress((void**)&zgp,  g_zg);
    cudaGetSymbolAddress((void**)&xdbl, g_xdbl);
    cudaGetSymbolAddress((void**)&delta,g_delta);
    cudaGetSymbolAddress((void**)&y2,   g_y2);
    cudaGetSymbolAddress((void**)&hff,  g_hff);

    stats_kernel<<<BB*KVAR, 256>>>(x);
    embed_kernel<<<TT, 128>>>(x, patch_w, patch_b, pos, vemb);

    for (int l = 0; l < NLAY; l++){
        const float* Wi  = in_w  + (size_t)l*(2*DIN)*DM;
        const float* Wx  = xp_w  + (size_t)l*64*DIN;
        const float* Wdt = dt_w  + (size_t)l*DIN*RNK;
        const float* bdt = dt_b  + (size_t)l*DIN;
        const float* Al  = A_log + (size_t)l*DIN*NST;
        const float* Dl  = D_par + (size_t)l*DIN;
        const float* Wo  = out_w + (size_t)l*DM*DIN;
        const float* W1  = ffn_w1+ (size_t)l*DFF*DM;
        const float* B1  = ffn_b1+ (size_t)l*DFF;
        const float* W2  = ffn_w2+ (size_t)l*DM*DFF;
        const float* B2  = ffn_b2+ (size_t)l*DM;

        // in_proj -> silu(u), zg
        gemm_nt<EP_SPLIT><<<dim3(32, TT/64), 256>>>(z, DM, Wi, DM, u, zgp, 0, nullptr, nullptr);
        // x_proj: xdbl = u @ Wx^T   (T,64)
        gemm_nt<EP_NONE><<<dim3(1, TT/64), 256>>>(u, DIN, Wx, DIN, xdbl, nullptr, 64, nullptr, nullptr);
        // delta = softplus(dt @ Wdt^T + bdt)
        gemm_nt<EP_SOFTPLUS><<<dim3(16, TT/64), 256>>>(xdbl, 64, Wdt, RNK, delta, nullptr, DIN, bdt, nullptr);
        // selective scan (fused +u*D, *silu(zg))
        scan_kernel<<<128, 256>>>(delta, u, zgp, xdbl, Al, Dl, y2);
        // out_proj + residual into tmp
        gemm_nt<EP_RES><<<dim3(8, TT/64), 256>>>(y2, DIN, Wo, DIN, tmp, nullptr, DM, nullptr, z);
        // LN(tmp)->z ; LN(z)->hln (ffn pre-norm)
        ln_kernel<true><<<TT/8, 256>>>(tmp, tmb_g + l*DM, tmb_b + l*DM, z,
                                       ffn_g + l*DM, ffn_b + l*DM, hln);
        // FFN
        gemm_nt<EP_GELU><<<dim3(32, TT/64), 256>>>(hln, DM, W1, DM, hff, nullptr, DFF, B1, nullptr);
        gemm_nt<EP_BIAS_RES><<<dim3(8, TT/64), 256>>>(hff, DFF, W2, DFF, z, nullptr, DM, B2, z);
    }

    // final LN -> tmp
    ln_kernel<false><<<TT/8, 256>>>(z, norm_g, norm_b, tmp, nullptr, nullptr, nullptr);
    // head
    head_partial<<<dim3(PP, 4), 256>>>(tmp, head_w);
    head_final<<<96, 256>>>(head_b, out);
    (void)in_sizes; (void)n_in; (void)out_size;
}

// round 2
// speedup vs baseline: 2.4522x; 2.4522x over previous
#include <cuda_runtime.h>
#include <math.h>

// ---------------- problem constants ----------------
#define BB     16
#define LCTX   512
#define KVAR   16
#define HPRED  96
#define DM     512
#define NST    16
#define NLAY   3
#define DFF    2048
#define PATCH  16
#define STRIDEP 8
#define PP     63            // (512-16)/8+1
#define DIN    1024          // 2*DM
#define RNK    32            // DT_RANK
#define SEQ    (KVAR*PP)     // 1008 tokens per batch
#define TT     (BB*SEQ)      // 16128 total tokens
#define EPSF   1e-5f
#define HWLD   (PP*DM)       // 32256 head_w row length

// ---------------- scratch (device globals; padded for scan prefetch) ----
__device__ float g_mean[BB*KVAR];
__device__ float g_std[BB*KVAR];
__device__ float g_z   [TT*DM];
__device__ float g_tmp [TT*DM];
__device__ float g_hln [TT*DM];
__device__ float g_u   [TT*DIN + DIN];
__device__ float g_zg  [TT*DIN + DIN];
__device__ float g_xdbl[TT*64 + 64];
__device__ float g_delta[TT*DIN + DIN];
__device__ float g_y2  [TT*DIN];
__device__ float g_hff [TT*DFF];
__device__ float g_headp[PP*BB*KVAR*HPRED];

// ---------------- helpers ----------------
__device__ __forceinline__ float siluf(float x){ return x / (1.f + __expf(-x)); }
__device__ __forceinline__ float softplusf(float x){
    return fmaxf(x, 0.f) + log1pf(expf(-fabsf(x)));
}
__device__ __forceinline__ float geluf(float x){
    return 0.5f * x * (1.f + erff(x * 0.70710678118654752f));
}

__device__ __forceinline__ void cp16(void* smem, const void* g){
    unsigned a = (unsigned)__cvta_generic_to_shared(smem);
    asm volatile("cp.async.cg.shared.global [%0], [%1], 16;" :: "r"(a), "l"(g));
}
__device__ __forceinline__ void cp_commit(){ asm volatile("cp.async.commit_group;"); }
__device__ __forceinline__ void cp_wait_all(){ asm volatile("cp.async.wait_group 0;"); }

__device__ __forceinline__ void mma_tf32(float* c, const unsigned* a, const unsigned* b){
    asm volatile("mma.sync.aligned.m16n8k8.row.col.f32.tf32.tf32.f32 "
        "{%0,%1,%2,%3}, {%4,%5,%6,%7}, {%8,%9}, {%0,%1,%2,%3};"
        : "+f"(c[0]),"+f"(c[1]),"+f"(c[2]),"+f"(c[3])
        : "r"(a[0]),"r"(a[1]),"r"(a[2]),"r"(a[3]), "r"(b[0]),"r"(b[1]));
}

// ---------------- per-(b,k) mean/std over L ----------------
__global__ void stats_kernel(const float* __restrict__ x){
    int bk = blockIdx.x; int b = bk >> 4, k = bk & 15;
    int tid = threadIdx.x;
    float s = 0.f, q = 0.f;
    for (int l = tid; l < LCTX; l += 256){
        float v = x[(b*LCTX + l)*KVAR + k];
        s += v; q += v*v;
    }
    __shared__ float sh[64];
#pragma unroll
    for (int o = 16; o; o >>= 1){
        s += __shfl_xor_sync(~0u, s, o);
        q += __shfl_xor_sync(~0u, q, o);
    }
    int w = tid >> 5;
    if ((tid & 31) == 0){ sh[w] = s; sh[w+32] = q; }
    __syncthreads();
    if (tid == 0){
        float S = 0.f, Q = 0.f;
        for (int i = 0; i < 8; i++){ S += sh[i]; Q += sh[32+i]; }
        float mu  = S * (1.f/LCTX);
        float var = Q * (1.f/LCTX) - mu*mu;
        g_mean[bk] = mu;
        g_std[bk]  = sqrtf(var + EPSF);
    }
}

// ---------------- patch embedding + pos + var embed ----------------
__global__ void embed_kernel(const float* __restrict__ x,
                             const float* __restrict__ pw,
                             const float* __restrict__ pb,
                             const float* __restrict__ pos,
                             const float* __restrict__ vemb){
    int row = blockIdx.x;                    // token row in [0,TT)
    int b = row / SEQ, rem = row % SEQ;
    int p = rem >> 4, k = rem & 15;
    int bk = b*KVAR + k;
    __shared__ float xs[PATCH];
    int tid = threadIdx.x;                   // 128
    if (tid < PATCH){
        float v = x[(b*LCTX + p*STRIDEP + tid)*KVAR + k];
        xs[tid] = (v - g_mean[bk]) / g_std[bk];
    }
    __syncthreads();
#pragma unroll
    for (int j = 0; j < 4; j++){
        int d = tid + j*128;
        float acc = pb[d] + pos[p*DM + d] + vemb[k*DM + d];
        const float4* w4 = (const float4*)(pw + d*PATCH);
#pragma unroll
        for (int t4 = 0; t4 < 4; t4++){
            float4 w = w4[t4];
            acc += xs[t4*4+0]*w.x + xs[t4*4+1]*w.y + xs[t4*4+2]*w.z + xs[t4*4+3]*w.w;
        }
        g_z[row*DM + d] = acc;
    }
}

// ---------------- tensor-core tf32 NT GEMM: C[M,N] = A[M,K] * W[N,K]^T -
// Block tile 128x64, 8 warps (4 in M x 2 in N), warp tile 32x32.
// cp.async double-buffered K stages of 16.
enum { EP_NONE=0, EP_SPLIT=1, EP_SOFTPLUS=2, EP_GELU=3, EP_BIAS_RES=4, EP_RES=5 };

template<int EP>
__global__ void __launch_bounds__(256) gemm_tc(const float* __restrict__ A, int lda,
                        const float* __restrict__ W, int Kd,
                        float* __restrict__ out0, float* __restrict__ out1, int ldo,
                        const float* __restrict__ bias, const float* __restrict__ res){
    __shared__ float As[2][128][20];   // pad 20 -> 80B row stride (16B aligned, bank-clean)
    __shared__ float Bs[2][64][20];
    int tid = threadIdx.x;
    int nt = blockIdx.x, mt = blockIdx.y;
    int lane = tid & 31, wid = tid >> 5;
    int warpM = wid & 3, warpN = wid >> 2;
    int grp = lane >> 2, tig = lane & 3;

    const float* Abase = A + (size_t)(mt*128)*lda;
    const float* Wbase = W + (size_t)(nt*64)*Kd;

    int aR0 = tid >> 2;            // rows 0..63
    int aK  = (tid & 3) * 4;
    int aR1 = aR0 + 64;            // rows 64..127
    int bR  = aR0;                 // rows 0..63

    float acc[2][4][4];
#pragma unroll
    for (int i = 0; i < 2; i++)
#pragma unroll
        for (int j = 0; j < 4; j++)
#pragma unroll
            for (int h = 0; h < 4; h++) acc[i][j][h] = 0.f;

    int nK = Kd >> 4;

    // prologue: stage 0
    cp16(&As[0][aR0][aK], Abase + (size_t)aR0*lda + aK);
    cp16(&As[0][aR1][aK], Abase + (size_t)aR1*lda + aK);
    cp16(&Bs[0][bR][aK],  Wbase + (size_t)bR*Kd  + aK);
    cp_commit();
    cp_wait_all();
    __syncthreads();

    int st = 0;
    for (int kt = 0; kt < nK; kt++){
        if (kt + 1 < nK){
            int ko = (kt+1)*16;
            cp16(&As[st^1][aR0][aK], Abase + (size_t)aR0*lda + ko + aK);
            cp16(&As[st^1][aR1][aK], Abase + (size_t)aR1*lda + ko + aK);
            cp16(&Bs[st^1][bR][aK],  Wbase + (size_t)bR*Kd  + ko + aK);
            cp_commit();
        }
#pragma unroll
        for (int k0 = 0; k0 < 16; k0 += 8){
            unsigned a[2][4], b[4][2];
#pragma unroll
            for (int i = 0; i < 2; i++){
                int r = warpM*32 + i*16;
                a[i][0] = __float_as_uint(As[st][r+grp  ][k0+tig  ]);
                a[i][1] = __float_as_uint(As[st][r+grp+8][k0+tig  ]);
                a[i][2] = __float_as_uint(As[st][r+grp  ][k0+tig+4]);
                a[i][3] = __float_as_uint(As[st][r+grp+8][k0+tig+4]);
            }
#pragma unroll
            for (int j = 0; j < 4; j++){
                int n = warpN*32 + j*8;
                b[j][0] = __float_as_uint(Bs[st][n+grp][k0+tig  ]);
                b[j][1] = __float_as_uint(Bs[st][n+grp][k0+tig+4]);
            }
#pragma unroll
            for (int i = 0; i < 2; i++)
#pragma unroll
                for (int j = 0; j < 4; j++)
                    mma_tf32(acc[i][j], a[i], b[j]);
        }
        cp_wait_all();
        __syncthreads();
        st ^= 1;
    }

    // epilogue
#pragma unroll
    for (int i = 0; i < 2; i++){
#pragma unroll
        for (int j = 0; j < 4; j++){
            int col = nt*64 + warpN*32 + j*8 + 2*tig;
#pragma unroll
            for (int h = 0; h < 2; h++){
                int row = mt*128 + warpM*32 + i*16 + grp + h*8;
                float v0 = acc[i][j][h*2+0];
                float v1 = acc[i][j][h*2+1];
                if (EP == EP_NONE){
                    out0[(size_t)row*ldo + col    ] = v0;
                    out0[(size_t)row*ldo + col + 1] = v1;
                } else if (EP == EP_SPLIT){
                    if (col < DIN){
                        out0[(size_t)row*DIN + col    ] = siluf(v0);
                        out0[(size_t)row*DIN + col + 1] = siluf(v1);
                    } else {
                        out1[(size_t)row*DIN + col - DIN    ] = v0;
                        out1[(size_t)row*DIN + col - DIN + 1] = v1;
                    }
                } else if (EP == EP_SOFTPLUS){
                    out0[(size_t)row*ldo + col    ] = softplusf(v0 + bias[col]);
                    out0[(size_t)row*ldo + col + 1] = softplusf(v1 + bias[col+1]);
                } else if (EP == EP_GELU){
                    out0[(size_t)row*ldo + col    ] = geluf(v0 + bias[col]);
                    out0[(size_t)row*ldo + col + 1] = geluf(v1 + bias[col+1]);
                } else if (EP == EP_BIAS_RES){
                    out0[(size_t)row*ldo + col    ] = v0 + bias[col]   + res[(size_t)row*ldo + col];
                    out0[(size_t)row*ldo + col + 1] = v1 + bias[col+1] + res[(size_t)row*ldo + col + 1];
                } else { // EP_RES
                    out0[(size_t)row*ldo + col    ] = v0 + res[(size_t)row*ldo + col];
                    out0[(size_t)row*ldo + col + 1] = v1 + res[(size_t)row*ldo + col + 1];
                }
            }
        }
    }
}

// ---------------- layer norm (warp per row of 512); optional 2nd LN ----
template<bool DOUBLE>
__global__ void ln_kernel(const float* __restrict__ in,
                          const float* __restrict__ g1, const float* __restrict__ b1,
                          float* __restrict__ o1,
                          const float* __restrict__ g2, const float* __restrict__ b2,
                          float* __restrict__ o2){
    int w = threadIdx.x >> 5, lane = threadIdx.x & 31;
    int row = blockIdx.x*8 + w;
    const float4* in4 = (const float4*)(in + (size_t)row*DM);
    float4 v[4];
    float s = 0.f, q = 0.f;
#pragma unroll
    for (int i = 0; i < 4; i++){
        v[i] = in4[lane + 32*i];
        s += v[i].x + v[i].y + v[i].z + v[i].w;
        q += v[i].x*v[i].x + v[i].y*v[i].y + v[i].z*v[i].z + v[i].w*v[i].w;
    }
#pragma unroll
    for (int o = 16; o; o >>= 1){
        s += __shfl_xor_sync(~0u, s, o);
        q += __shfl_xor_sync(~0u, q, o);
    }
    float mu = s * (1.f/DM);
    float rs = rsqrtf(q*(1.f/DM) - mu*mu + EPSF);
    float4 zz[4];
    float s2 = 0.f, q2 = 0.f;
#pragma unroll
    for (int i = 0; i < 4; i++){
        float4 gg = ((const float4*)g1)[lane + 32*i];
        float4 bb = ((const float4*)b1)[lane + 32*i];
        zz[i].x = (v[i].x - mu)*rs*gg.x + bb.x;
        zz[i].y = (v[i].y - mu)*rs*gg.y + bb.y;
        zz[i].z = (v[i].z - mu)*rs*gg.z + bb.z;
        zz[i].w = (v[i].w - mu)*rs*gg.w + bb.w;
        if (DOUBLE){
            s2 += zz[i].x + zz[i].y + zz[i].z + zz[i].w;
            q2 += zz[i].x*zz[i].x + zz[i].y*zz[i].y + zz[i].z*zz[i].z + zz[i].w*zz[i].w;
        }
        ((float4*)(o1 + (size_t)row*DM))[lane + 32*i] = zz[i];
    }
    if (DOUBLE){
#pragma unroll
        for (int o = 16; o; o >>= 1){
            s2 += __shfl_xor_sync(~0u, s2, o);
            q2 += __shfl_xor_sync(~0u, q2, o);
        }
        float mu2 = s2 * (1.f/DM);
        float rs2 = rsqrtf(q2*(1.f/DM) - mu2*mu2 + EPSF);
#pragma unroll
        for (int i = 0; i < 4; i++){
            float4 gg = ((const float4*)g2)[lane + 32*i];
            float4 bb = ((const float4*)b2)[lane + 32*i];
            float4 o4;
            o4.x = (zz[i].x - mu2)*rs2*gg.x + bb.x;
            o4.y = (zz[i].y - mu2)*rs2*gg.y + bb.y;
            o4.z = (zz[i].z - mu2)*rs2*gg.z + bb.z;
            o4.w = (zz[i].w - mu2)*rs2*gg.w + bb.w;
            ((float4*)(o2 + (size_t)row*DM))[lane + 32*i] = o4;
        }
    }
}

// ---------------- selective scan ----------------
__global__ void scan_kernel(const float* __restrict__ delta,
                            const float* __restrict__ u,
                            const float* __restrict__ zg,
                            const float* __restrict__ xdbl,
                            const float* __restrict__ A_log,
                            const float* __restrict__ Dp,
                            float* __restrict__ y2){
    int blk = blockIdx.x;                    // 128 blocks
    int b = blk >> 3, dblk = blk & 7;
    int t = threadIdx.x;                     // 256
    int half = t & 1;
    int d = dblk*128 + (t >> 1);
    int nb = half * 8;

    float Aa[8];
#pragma unroll
    for (int j = 0; j < 8; j++) Aa[j] = -expf(A_log[d*NST + nb + j]);
    float A0 = Aa[0];
    float stepA = Aa[1] - Aa[0];
    bool prog = true;
#pragma unroll
    for (int j = 0; j < 8; j++){
        float e = A0 + (float)j * stepA;
        if (fabsf(Aa[j] - e) > 1e-5f*fabsf(e) + 1e-7f) prog = false;
    }
    float Dd = Dp[d];

    float h[8];
#pragma unroll
    for (int j = 0; j < 8; j++) h[j] = 0.f;

    size_t base = (size_t)(b*SEQ)*DIN + d;
    const float* xb = xdbl + (size_t)(b*SEQ)*64 + 32 + nb;

    float dv = delta[base], uv = u[base], zv = zg[base];
    float4 B0 = *(const float4*)(xb);
    float4 B1 = *(const float4*)(xb + 4);
    float4 C0 = *(const float4*)(xb + 16);
    float4 C1 = *(const float4*)(xb + 20);

    for (int s = 0; s < SEQ; s++){
        size_t baseN = base + DIN;
        const float* xbN = xb + 64;
        float dvN = delta[baseN], uvN = u[baseN], zvN = zg[baseN];
        float4 B0N = *(const float4*)(xbN);
        float4 B1N = *(const float4*)(xbN + 4);
        float4 C0N = *(const float4*)(xbN + 16);
        float4 C1N = *(const float4*)(xbN + 20);

        float du = dv * uv;
        float y = 0.f;
        if (prog){
            float e = __expf(dv * A0);
            float r = __expf(dv * stepA);
            h[0] = h[0]*e + du*B0.x; y += h[0]*C0.x; e *= r;
            h[1] = h[1]*e + du*B0.y; y += h[1]*C0.y; e *= r;
            h[2] = h[2]*e + du*B0.z; y += h[2]*C0.z; e *= r;
            h[3] = h[3]*e + du*B0.w; y += h[3]*C0.w; e *= r;
            h[4] = h[4]*e + du*B1.x; y += h[4]*C1.x; e *= r;
            h[5] = h[5]*e + du*B1.y; y += h[5]*C1.y; e *= r;
            h[6] = h[6]*e + du*B1.z; y += h[6]*C1.z; e *= r;
            h[7] = h[7]*e + du*B1.w; y += h[7]*C1.w;
        } else {
            float Bv[8] = {B0.x,B0.y,B0.z,B0.w,B1.x,B1.y,B1.z,B1.w};
            float Cv[8] = {C0.x,C0.y,C0.z,C0.w,C1.x,C1.y,C1.z,C1.w};
#pragma unroll
            for (int j = 0; j < 8; j++){
                float e = __expf(dv * Aa[j]);
                h[j] = h[j]*e + du*Bv[j];
                y += h[j]*Cv[j];
            }
        }
        float ysum = y + __shfl_xor_sync(~0u, y, 1);
        if (!half){
            float out = (ysum + uv*Dd) * siluf(zv);
            y2[base] = out;
        }
        base = baseN; xb = xbN;
        dv = dvN; uv = uvN; zv = zvN;
        B0 = B0N; B1 = B1N; C0 = C0N; C1 = C1N;
    }
}

// ---------------- head: partial GEMM per patch index p ----------------
__global__ void head_partial(const float* __restrict__ zf, const float* __restrict__ hw){
    int p = blockIdx.x, mt = blockIdx.y;     // p in [0,63), mt in [0,4)
    __shared__ float As[16][64];
    __shared__ float Ws[16][96];
    int tid = threadIdx.x;                   // 256
    int lm = tid >> 2, lk = (tid & 3) * 4;
    int bkrow = mt*64 + lm;
    int b = bkrow >> 4, kk = bkrow & 15;
    const float* Ag = zf + (size_t)(b*SEQ + p*KVAR + kk)*DM + lk;
    int tx = tid & 15, ty = tid >> 4;
    float acc[4][6];
#pragma unroll
    for (int i = 0; i < 4; i++)
#pragma unroll
        for (int j = 0; j < 6; j++) acc[i][j] = 0.f;

    for (int kt = 0; kt < DM; kt += 16){
        float4 av = *(const float4*)(Ag + kt);
        As[lk+0][lm]=av.x; As[lk+1][lm]=av.y; As[lk+2][lm]=av.z; As[lk+3][lm]=av.w;
#pragma unroll
        for (int i = 0; i < 6; i++){
            int e = tid + i*256;             // 1536 = 96*16 elements
            int n = e >> 4, kq = e & 15;
            Ws[kq][n] = hw[(size_t)n*HWLD + p*DM + kt + kq];
        }
        __syncthreads();
#pragma unroll
        for (int k = 0; k < 16; k++){
            float4 a = *(const float4*)&As[k][ty*4];
            float av4[4] = {a.x, a.y, a.z, a.w};
#pragma unroll
            for (int j = 0; j < 6; j++){
                float wv = Ws[k][tx*6 + j];
#pragma unroll
                for (int i = 0; i < 4; i++) acc[i][j] += av4[i]*wv;
            }
        }
        __syncthreads();
    }
#pragma unroll
    for (int i = 0; i < 4; i++)
#pragma unroll
        for (int j = 0; j < 6; j++)
            g_headp[(size_t)(p*256 + mt*64 + ty*4 + i)*HPRED + tx*6 + j] = acc[i][j];
}

// ---------------- head reduction + de-normalization ----------------
__global__ void head_final(const float* __restrict__ hb, float* __restrict__ out){
    int idx = blockIdx.x*256 + threadIdx.x;  // 24576 = 256*96
    int bk = idx / HPRED, hh = idx % HPRED;
    float s = 0.f;
    for (int p = 0; p < PP; p++) s += g_headp[(size_t)p*(BB*KVAR*HPRED) + idx];
    s += hb[hh];
    int b = bk >> 4, k = bk & 15;
    out[b*(HPRED*KVAR) + hh*KVAR + k] = s * g_std[bk] + g_mean[bk];
}

// ---------------- launch ----------------
extern "C" void kernel_launch(void* const* d_in, const int* in_sizes, int n_in,
                              void* d_out, int out_size){
    const float* x        = (const float*)d_in[0];
    const float* patch_w  = (const float*)d_in[1];
    const float* patch_b  = (const float*)d_in[2];
    const float* pos      = (const float*)d_in[3];
    const float* vemb     = (const float*)d_in[4];
    const float* in_w     = (const float*)d_in[5];
    const float* xp_w     = (const float*)d_in[6];
    const float* dt_w     = (const float*)d_in[7];
    const float* dt_b     = (const float*)d_in[8];
    const float* A_log    = (const float*)d_in[9];
    const float* D_par    = (const float*)d_in[10];
    const float* out_w    = (const float*)d_in[11];
    const float* tmb_g    = (const float*)d_in[12];
    const float* tmb_b    = (const float*)d_in[13];
    const float* ffn_g    = (const float*)d_in[14];
    const float* ffn_b    = (const float*)d_in[15];
    const float* ffn_w1   = (const float*)d_in[16];
    const float* ffn_b1   = (const float*)d_in[17];
    const float* ffn_w2   = (const float*)d_in[18];
    const float* ffn_b2   = (const float*)d_in[19];
    const float* norm_g   = (const float*)d_in[20];
    const float* norm_b   = (const float*)d_in[21];
    const float* head_w   = (const float*)d_in[22];
    const float* head_b   = (const float*)d_in[23];
    float* out = (float*)d_out;

    float *z, *tmp, *hln, *u, *zgp, *xdbl, *delta, *y2, *hff;
    cudaGetSymbolAddress((void**)&z,    g_z);
    cudaGetSymbolAddress((void**)&tmp,  g_tmp);
    cudaGetSymbolAddress((void**)&hln,  g_hln);
    cudaGetSymbolAddress((void**)&u,    g_u);
    cudaGetSymbolAddress((void**)&zgp,  g_zg);
    cudaGetSymbolAddress((void**)&xdbl, g_xdbl);
    cudaGetSymbolAddress((void**)&delta,g_delta);
    cudaGetSymbolAddress((void**)&y2,   g_y2);
    cudaGetSymbolAddress((void**)&hff,  g_hff);

    stats_kernel<<<BB*KVAR, 256>>>(x);
    embed_kernel<<<TT, 128>>>(x, patch_w, patch_b, pos, vemb);

    const int MT = TT/128;   // 126 M tiles

    for (int l = 0; l < NLAY; l++){
        const float* Wi  = in_w  + (size_t)l*(2*DIN)*DM;
        const float* Wx  = xp_w  + (size_t)l*64*DIN;
        const float* Wdt = dt_w  + (size_t)l*DIN*RNK;
        const float* bdt = dt_b  + (size_t)l*DIN;
        const float* Al  = A_log + (size_t)l*DIN*NST;
        const float* Dl  = D_par + (size_t)l*DIN;
        const float* Wo  = out_w + (size_t)l*DM*DIN;
        const float* W1  = ffn_w1+ (size_t)l*DFF*DM;
        const float* B1  = ffn_b1+ (size_t)l*DFF;
        const float* W2  = ffn_w2+ (size_t)l*DM*DFF;
        const float* B2  = ffn_b2+ (size_t)l*DM;

        // in_proj -> silu(u), zg   (N=2048)
        gemm_tc<EP_SPLIT><<<dim3(32, MT), 256>>>(z, DM, Wi, DM, u, zgp, 0, nullptr, nullptr);
        // x_proj: xdbl = u @ Wx^T   (N=64)
        gemm_tc<EP_NONE><<<dim3(1, MT), 256>>>(u, DIN, Wx, DIN, xdbl, nullptr, 64, nullptr, nullptr);
        // delta = softplus(dt @ Wdt^T + bdt)  (N=1024, K=32)
        gemm_tc<EP_SOFTPLUS><<<dim3(16, MT), 256>>>(xdbl, 64, Wdt, RNK, delta, nullptr, DIN, bdt, nullptr);
        // selective scan (fused +u*D, *silu(zg))
        scan_kernel<<<128, 256>>>(delta, u, zgp, xdbl, Al, Dl, y2);
        // out_proj + residual into tmp  (N=512, K=1024)
        gemm_tc<EP_RES><<<dim3(8, MT), 256>>>(y2, DIN, Wo, DIN, tmp, nullptr, DM, nullptr, z);
        // LN(tmp)->z ; LN(z)->hln (ffn pre-norm)
        ln_kernel<true><<<TT/8, 256>>>(tmp, tmb_g + l*DM, tmb_b + l*DM, z,
                                       ffn_g + l*DM, ffn_b + l*DM, hln);
        // FFN
        gemm_tc<EP_GELU><<<dim3(32, MT), 256>>>(hln, DM, W1, DM, hff, nullptr, DFF, B1, nullptr);
        gemm_tc<EP_BIAS_RES><<<dim3(8, MT), 256>>>(hff, DFF, W2, DFF, z, nullptr, DM, B2, z);
    }

    // final LN -> tmp
    ln_kernel<false><<<TT/8, 256>>>(z, norm_g, norm_b, tmp, nullptr, nullptr, nullptr);
    // head
    head_partial<<<dim3(PP, 4), 256>>>(tmp, head_w);
    head_final<<<96, 256>>>(head_b, out);
    (void)in_sizes; (void)n_in; (void)out_size;
}

// round 3
// speedup vs baseline: 2.5613x; 1.0445x over previous
#include <cuda_runtime.h>
#include <math.h>

// ---------------- problem constants ----------------
#define BB     16
#define LCTX   512
#define KVAR   16
#define HPRED  96
#define DM     512
#define NST    16
#define NLAY   3
#define DFF    2048
#define PATCH  16
#define STRIDEP 8
#define PP     63            // (512-16)/8+1
#define DIN    1024          // 2*DM
#define RNK    32            // DT_RANK
#define SEQ    (KVAR*PP)     // 1008 tokens per batch
#define TT     (BB*SEQ)      // 16128 total tokens
#define EPSF   1e-5f
#define HWLD   (PP*DM)       // 32256 head_w row length

// ---------------- scratch (device globals; padded for scan prefetch) ----
__device__ float g_mean[BB*KVAR];
__device__ float g_std[BB*KVAR];
__device__ float g_z   [TT*DM];
__device__ float g_tmp [TT*DM];
__device__ float g_hln [TT*DM];
__device__ float g_u   [TT*DIN + DIN];
__device__ float g_zg  [TT*DIN + DIN];
__device__ float g_xdbl[TT*64 + 64];
__device__ float g_delta[TT*DIN + DIN];
__device__ float g_y2  [TT*DIN];
__device__ float g_hff [TT*DFF];
__device__ float g_headp[PP*BB*KVAR*HPRED];

// ---------------- helpers ----------------
__device__ __forceinline__ float siluf(float x){ return x / (1.f + __expf(-x)); }
__device__ __forceinline__ float softplusf(float x){
    return fmaxf(x, 0.f) + log1pf(expf(-fabsf(x)));
}
__device__ __forceinline__ float geluf(float x){
    return 0.5f * x * (1.f + erff(x * 0.70710678118654752f));
}

__device__ __forceinline__ void cp16(void* smem, const void* g){
    unsigned a = (unsigned)__cvta_generic_to_shared(smem);
    asm volatile("cp.async.cg.shared.global [%0], [%1], 16;" :: "r"(a), "l"(g));
}
__device__ __forceinline__ void cp_commit(){ asm volatile("cp.async.commit_group;"); }
__device__ __forceinline__ void cp_wait_all(){ asm volatile("cp.async.wait_group 0;"); }

__device__ __forceinline__ void mma_tf32(float* c, const unsigned* a, const unsigned* b){
    asm volatile("mma.sync.aligned.m16n8k8.row.col.f32.tf32.tf32.f32 "
        "{%0,%1,%2,%3}, {%4,%5,%6,%7}, {%8,%9}, {%0,%1,%2,%3};"
        : "+f"(c[0]),"+f"(c[1]),"+f"(c[2]),"+f"(c[3])
        : "r"(a[0]),"r"(a[1]),"r"(a[2]),"r"(a[3]), "r"(b[0]),"r"(b[1]));
}

// ---------------- per-(b,k) mean/std over L ----------------
__global__ void stats_kernel(const float* __restrict__ x){
    int bk = blockIdx.x; int b = bk >> 4, k = bk & 15;
    int tid = threadIdx.x;
    float s = 0.f, q = 0.f;
    for (int l = tid; l < LCTX; l += 256){
        float v = x[(b*LCTX + l)*KVAR + k];
        s += v; q += v*v;
    }
    __shared__ float sh[64];
#pragma unroll
    for (int o = 16; o; o >>= 1){
        s += __shfl_xor_sync(~0u, s, o);
        q += __shfl_xor_sync(~0u, q, o);
    }
    int w = tid >> 5;
    if ((tid & 31) == 0){ sh[w] = s; sh[w+32] = q; }
    __syncthreads();
    if (tid == 0){
        float S = 0.f, Q = 0.f;
        for (int i = 0; i < 8; i++){ S += sh[i]; Q += sh[32+i]; }
        float mu  = S * (1.f/LCTX);
        float var = Q * (1.f/LCTX) - mu*mu;
        g_mean[bk] = mu;
        g_std[bk]  = sqrtf(var + EPSF);
    }
}

// ---------------- patch embedding + pos + var embed ----------------
__global__ void embed_kernel(const float* __restrict__ x,
                             const float* __restrict__ pw,
                             const float* __restrict__ pb,
                             const float* __restrict__ pos,
                             const float* __restrict__ vemb){
    int row = blockIdx.x;                    // token row in [0,TT)
    int b = row / SEQ, rem = row % SEQ;
    int p = rem >> 4, k = rem & 15;
    int bk = b*KVAR + k;
    __shared__ float xs[PATCH];
    int tid = threadIdx.x;                   // 128
    if (tid < PATCH){
        float v = x[(b*LCTX + p*STRIDEP + tid)*KVAR + k];
        xs[tid] = (v - g_mean[bk]) / g_std[bk];
    }
    __syncthreads();
#pragma unroll
    for (int j = 0; j < 4; j++){
        int d = tid + j*128;
        float acc = pb[d] + pos[p*DM + d] + vemb[k*DM + d];
        const float4* w4 = (const float4*)(pw + d*PATCH);
#pragma unroll
        for (int t4 = 0; t4 < 4; t4++){
            float4 w = w4[t4];
            acc += xs[t4*4+0]*w.x + xs[t4*4+1]*w.y + xs[t4*4+2]*w.z + xs[t4*4+3]*w.w;
        }
        g_z[row*DM + d] = acc;
    }
}

// ---------------- epilogue modes ----------------
enum { EP_NONE=0, EP_SPLIT=1, EP_SOFTPLUS=2, EP_GELU=3, EP_BIAS_RES=4, EP_RES=5 };

template<int EP>
__device__ __forceinline__ void ep_store(float* __restrict__ out0, float* __restrict__ out1,
                                         int ldo, const float* __restrict__ bias,
                                         const float* __restrict__ res,
                                         int row, int col, float v0, float v1){
    if (EP == EP_NONE){
        out0[(size_t)row*ldo + col    ] = v0;
        out0[(size_t)row*ldo + col + 1] = v1;
    } else if (EP == EP_SPLIT){
        if (col < DIN){
            out0[(size_t)row*DIN + col    ] = siluf(v0);
            out0[(size_t)row*DIN + col + 1] = siluf(v1);
        } else {
            out1[(size_t)row*DIN + col - DIN    ] = v0;
            out1[(size_t)row*DIN + col - DIN + 1] = v1;
        }
    } else if (EP == EP_SOFTPLUS){
        out0[(size_t)row*ldo + col    ] = softplusf(v0 + bias[col]);
        out0[(size_t)row*ldo + col + 1] = softplusf(v1 + bias[col+1]);
    } else if (EP == EP_GELU){
        out0[(size_t)row*ldo + col    ] = geluf(v0 + bias[col]);
        out0[(size_t)row*ldo + col + 1] = geluf(v1 + bias[col+1]);
    } else if (EP == EP_BIAS_RES){
        out0[(size_t)row*ldo + col    ] = v0 + bias[col]   + res[(size_t)row*ldo + col];
        out0[(size_t)row*ldo + col + 1] = v1 + bias[col+1] + res[(size_t)row*ldo + col + 1];
    } else { // EP_RES
        out0[(size_t)row*ldo + col    ] = v0 + res[(size_t)row*ldo + col];
        out0[(size_t)row*ldo + col + 1] = v1 + res[(size_t)row*ldo + col + 1];
    }
}

// ---------------- tf32 NT GEMM, 128x128 block, warp tile 64x32 ----------
// 8 warps as 2(M) x 4(N). cp.async double-buffered BK=16.
template<int EP>
__global__ void __launch_bounds__(256) gemm_tc(const float* __restrict__ A, int lda,
                        const float* __restrict__ W, int Kd,
                        float* __restrict__ out0, float* __restrict__ out1, int ldo,
                        const float* __restrict__ bias, const float* __restrict__ res){
    __shared__ float As[2][128][20];
    __shared__ float Bs[2][128][20];
    int tid = threadIdx.x;
    int nt = blockIdx.x, mt = blockIdx.y;
    int lane = tid & 31, wid = tid >> 5;
    int warpM = wid & 1, warpN = wid >> 1;      // 2 x 4
    int grp = lane >> 2, tig = lane & 3;

    const float* Abase = A + (size_t)(mt*128)*lda;
    const float* Wbase = W + (size_t)(nt*128)*Kd;

    int r  = tid >> 2;              // 0..63
    int kk = (tid & 3) * 4;

    float acc[4][4][4];
#pragma unroll
    for (int i = 0; i < 4; i++)
#pragma unroll
        for (int j = 0; j < 4; j++)
#pragma unroll
            for (int h = 0; h < 4; h++) acc[i][j][h] = 0.f;

    int nK = Kd >> 4;

    cp16(&As[0][r   ][kk], Abase + (size_t)r*lda        + kk);
    cp16(&As[0][r+64][kk], Abase + (size_t)(r+64)*lda   + kk);
    cp16(&Bs[0][r   ][kk], Wbase + (size_t)r*Kd         + kk);
    cp16(&Bs[0][r+64][kk], Wbase + (size_t)(r+64)*Kd    + kk);
    cp_commit();
    cp_wait_all();
    __syncthreads();

    int st = 0;
    for (int kt = 0; kt < nK; kt++){
        if (kt + 1 < nK){
            int ko = (kt+1)*16;
            cp16(&As[st^1][r   ][kk], Abase + (size_t)r*lda      + ko + kk);
            cp16(&As[st^1][r+64][kk], Abase + (size_t)(r+64)*lda + ko + kk);
            cp16(&Bs[st^1][r   ][kk], Wbase + (size_t)r*Kd       + ko + kk);
            cp16(&Bs[st^1][r+64][kk], Wbase + (size_t)(r+64)*Kd  + ko + kk);
            cp_commit();
        }
#pragma unroll
        for (int k0 = 0; k0 < 16; k0 += 8){
            unsigned a[4][4], b[4][2];
#pragma unroll
            for (int i = 0; i < 4; i++){
                int row = warpM*64 + i*16;
                a[i][0] = __float_as_uint(As[st][row+grp  ][k0+tig  ]);
                a[i][1] = __float_as_uint(As[st][row+grp+8][k0+tig  ]);
                a[i][2] = __float_as_uint(As[st][row+grp  ][k0+tig+4]);
                a[i][3] = __float_as_uint(As[st][row+grp+8][k0+tig+4]);
            }
#pragma unroll
            for (int j = 0; j < 4; j++){
                int n = warpN*32 + j*8;
                b[j][0] = __float_as_uint(Bs[st][n+grp][k0+tig  ]);
                b[j][1] = __float_as_uint(Bs[st][n+grp][k0+tig+4]);
            }
#pragma unroll
            for (int i = 0; i < 4; i++)
#pragma unroll
                for (int j = 0; j < 4; j++)
                    mma_tf32(acc[i][j], a[i], b[j]);
        }
        cp_wait_all();
        __syncthreads();
        st ^= 1;
    }

#pragma unroll
    for (int i = 0; i < 4; i++){
#pragma unroll
        for (int j = 0; j < 4; j++){
            int col = nt*128 + warpN*32 + j*8 + 2*tig;
#pragma unroll
            for (int h = 0; h < 2; h++){
                int row = mt*128 + warpM*64 + i*16 + grp + h*8;
                ep_store<EP>(out0, out1, ldo, bias, res, row, col,
                             acc[i][j][h*2+0], acc[i][j][h*2+1]);
            }
        }
    }
}

// ---------------- tf32 NT GEMM, 64x64 block (for small N) ---------------
// 4 warps as 2(M) x 2(N), warp tile 32x32, cp.async double-buffered BK=16.
template<int EP>
__global__ void __launch_bounds__(128) gemm_tc64(const float* __restrict__ A, int lda,
                        const float* __restrict__ W, int Kd,
                        float* __restrict__ out0, float* __restrict__ out1, int ldo,
                        const float* __restrict__ bias, const float* __restrict__ res){
    __shared__ float As[2][64][20];
    __shared__ float Bs[2][64][20];
    int tid = threadIdx.x;
    int nt = blockIdx.x, mt = blockIdx.y;
    int lane = tid & 31, wid = tid >> 5;
    int warpM = wid & 1, warpN = wid >> 1;      // 2 x 2
    int grp = lane >> 2, tig = lane & 3;

    const float* Abase = A + (size_t)(mt*64)*lda;
    const float* Wbase = W + (size_t)(nt*64)*Kd;

    int r  = tid >> 2;              // 0..31
    int kk = (tid & 3) * 4;

    float acc[2][4][4];
#pragma unroll
    for (int i = 0; i < 2; i++)
#pragma unroll
        for (int j = 0; j < 4; j++)
#pragma unroll
            for (int h = 0; h < 4; h++) acc[i][j][h] = 0.f;

    int nK = Kd >> 4;

    cp16(&As[0][r   ][kk], Abase + (size_t)r*lda      + kk);
    cp16(&As[0][r+32][kk], Abase + (size_t)(r+32)*lda + kk);
    cp16(&Bs[0][r   ][kk], Wbase + (size_t)r*Kd       + kk);
    cp16(&Bs[0][r+32][kk], Wbase + (size_t)(r+32)*Kd  + kk);
    cp_commit();
    cp_wait_all();
    __syncthreads();

    int st = 0;
    for (int kt = 0; kt < nK; kt++){
        if (kt + 1 < nK){
            int ko = (kt+1)*16;
            cp16(&As[st^1][r   ][kk], Abase + (size_t)r*lda      + ko + kk);
            cp16(&As[st^1][r+32][kk], Abase + (size_t)(r+32)*lda + ko + kk);
            cp16(&Bs[st^1][r   ][kk], Wbase + (size_t)r*Kd       + ko + kk);
            cp16(&Bs[st^1][r+32][kk], Wbase + (size_t)(r+32)*Kd  + ko + kk);
            cp_commit();
        }
#pragma unroll
        for (int k0 = 0; k0 < 16; k0 += 8){
            unsigned a[2][4], b[4][2];
#pragma unroll
            for (int i = 0; i < 2; i++){
                int row = warpM*32 + i*16;
                a[i][0] = __float_as_uint(As[st][row+grp  ][k0+tig  ]);
                a[i][1] = __float_as_uint(As[st][row+grp+8][k0+tig  ]);
                a[i][2] = __float_as_uint(As[st][row+grp  ][k0+tig+4]);
                a[i][3] = __float_as_uint(As[st][row+grp+8][k0+tig+4]);
            }
#pragma unroll
            for (int j = 0; j < 4; j++){
                int n = warpN*32 + j*8;
                b[j][0] = __float_as_uint(Bs[st][n+grp][k0+tig  ]);
                b[j][1] = __float_as_uint(Bs[st][n+grp][k0+tig+4]);
            }
#pragma unroll
            for (int i = 0; i < 2; i++)
#pragma unroll
                for (int j = 0; j < 4; j++)
                    mma_tf32(acc[i][j], a[i], b[j]);
        }
        cp_wait_all();
        __syncthreads();
        st ^= 1;
    }

#pragma unroll
    for (int i = 0; i < 2; i++){
#pragma unroll
        for (int j = 0; j < 4; j++){
            int col = nt*64 + warpN*32 + j*8 + 2*tig;
#pragma unroll
            for (int h = 0; h < 2; h++){
                int row = mt*64 + warpM*32 + i*16 + grp + h*8;
                ep_store<EP>(out0, out1, ldo, bias, res, row, col,
                             acc[i][j][h*2+0], acc[i][j][h*2+1]);
            }
        }
    }
}

// ---------------- layer norm (warp per row of 512); optional 2nd LN ----
template<bool DOUBLE>
__global__ void ln_kernel(const float* __restrict__ in,
                          const float* __restrict__ g1, const float* __restrict__ b1,
                          float* __restrict__ o1,
                          const float* __restrict__ g2, const float* __restrict__ b2,
                          float* __restrict__ o2){
    int w = threadIdx.x >> 5, lane = threadIdx.x & 31;
    int row = blockIdx.x*8 + w;
    const float4* in4 = (const float4*)(in + (size_t)row*DM);
    float4 v[4];
    float s = 0.f, q = 0.f;
#pragma unroll
    for (int i = 0; i < 4; i++){
        v[i] = in4[lane + 32*i];
        s += v[i].x + v[i].y + v[i].z + v[i].w;
        q += v[i].x*v[i].x + v[i].y*v[i].y + v[i].z*v[i].z + v[i].w*v[i].w;
    }
#pragma unroll
    for (int o = 16; o; o >>= 1){
        s += __shfl_xor_sync(~0u, s, o);
        q += __shfl_xor_sync(~0u, q, o);
    }
    float mu = s * (1.f/DM);
    float rs = rsqrtf(q*(1.f/DM) - mu*mu + EPSF);
    float4 zz[4];
    float s2 = 0.f, q2 = 0.f;
#pragma unroll
    for (int i = 0; i < 4; i++){
        float4 gg = ((const float4*)g1)[lane + 32*i];
        float4 bb = ((const float4*)b1)[lane + 32*i];
        zz[i].x = (v[i].x - mu)*rs*gg.x + bb.x;
        zz[i].y = (v[i].y - mu)*rs*gg.y + bb.y;
        zz[i].z = (v[i].z - mu)*rs*gg.z + bb.z;
        zz[i].w = (v[i].w - mu)*rs*gg.w + bb.w;
        if (DOUBLE){
            s2 += zz[i].x + zz[i].y + zz[i].z + zz[i].w;
            q2 += zz[i].x*zz[i].x + zz[i].y*zz[i].y + zz[i].z*zz[i].z + zz[i].w*zz[i].w;
        }
        ((float4*)(o1 + (size_t)row*DM))[lane + 32*i] = zz[i];
    }
    if (DOUBLE){
#pragma unroll
        for (int o = 16; o; o >>= 1){
            s2 += __shfl_xor_sync(~0u, s2, o);
            q2 += __shfl_xor_sync(~0u, q2, o);
        }
        float mu2 = s2 * (1.f/DM);
        float rs2 = rsqrtf(q2*(1.f/DM) - mu2*mu2 + EPSF);
#pragma unroll
        for (int i = 0; i < 4; i++){
            float4 gg = ((const float4*)g2)[lane + 32*i];
            float4 bb = ((const float4*)b2)[lane + 32*i];
            float4 o4;
            o4.x = (zz[i].x - mu2)*rs2*gg.x + bb.x;
            o4.y = (zz[i].y - mu2)*rs2*gg.y + bb.y;
            o4.z = (zz[i].z - mu2)*rs2*gg.z + bb.z;
            o4.w = (zz[i].w - mu2)*rs2*gg.w + bb.w;
            ((float4*)(o2 + (size_t)row*DM))[lane + 32*i] = o4;
        }
    }
}

// ---------------- selective scan ----------------
__global__ void scan_kernel(const float* __restrict__ delta,
                            const float* __restrict__ u,
                            const float* __restrict__ zg,
                            const float* __restrict__ xdbl,
                            const float* __restrict__ A_log,
                            const float* __restrict__ Dp,
                            float* __restrict__ y2){
    int blk = blockIdx.x;                    // 128 blocks
    int b = blk >> 3, dblk = blk & 7;
    int t = threadIdx.x;                     // 256
    int half = t & 1;
    int d = dblk*128 + (t >> 1);
    int nb = half * 8;

    float Aa[8];
#pragma unroll
    for (int j = 0; j < 8; j++) Aa[j] = -expf(A_log[d*NST + nb + j]);
    float A0 = Aa[0];
    float stepA = Aa[1] - Aa[0];
    bool prog = true;
#pragma unroll
    for (int j = 0; j < 8; j++){
        float e = A0 + (float)j * stepA;
        if (fabsf(Aa[j] - e) > 1e-5f*fabsf(e) + 1e-7f) prog = false;
    }
    float Dd = Dp[d];

    float h[8];
#pragma unroll
    for (int j = 0; j < 8; j++) h[j] = 0.f;

    size_t base = (size_t)(b*SEQ)*DIN + d;
    const float* xb = xdbl + (size_t)(b*SEQ)*64 + 32 + nb;

    float dv = delta[base], uv = u[base], zv = zg[base];
    float4 B0 = *(const float4*)(xb);
    float4 B1 = *(const float4*)(xb + 4);
    float4 C0 = *(const float4*)(xb + 16);
    float4 C1 = *(const float4*)(xb + 20);

    for (int s = 0; s < SEQ; s++){
        size_t baseN = base + DIN;
        const float* xbN = xb + 64;
        float dvN = delta[baseN], uvN = u[baseN], zvN = zg[baseN];
        float4 B0N = *(const float4*)(xbN);
        float4 B1N = *(const float4*)(xbN + 4);
        float4 C0N = *(const float4*)(xbN + 16);
        float4 C1N = *(const float4*)(xbN + 20);

        float du = dv * uv;
        float y = 0.f;
        if (prog){
            float e = __expf(dv * A0);
            float r = __expf(dv * stepA);
            h[0] = h[0]*e + du*B0.x; y += h[0]*C0.x; e *= r;
            h[1] = h[1]*e + du*B0.y; y += h[1]*C0.y; e *= r;
            h[2] = h[2]*e + du*B0.z; y += h[2]*C0.z; e *= r;
            h[3] = h[3]*e + du*B0.w; y += h[3]*C0.w; e *= r;
            h[4] = h[4]*e + du*B1.x; y += h[4]*C1.x; e *= r;
            h[5] = h[5]*e + du*B1.y; y += h[5]*C1.y; e *= r;
            h[6] = h[6]*e + du*B1.z; y += h[6]*C1.z; e *= r;
            h[7] = h[7]*e + du*B1.w; y += h[7]*C1.w;
        } else {
            float Bv[8] = {B0.x,B0.y,B0.z,B0.w,B1.x,B1.y,B1.z,B1.w};
            float Cv[8] = {C0.x,C0.y,C0.z,C0.w,C1.x,C1.y,C1.z,C1.w};
#pragma unroll
            for (int j = 0; j < 8; j++){
                float e = __expf(dv * Aa[j]);
                h[j] = h[j]*e + du*Bv[j];
                y += h[j]*Cv[j];
            }
        }
        float ysum = y + __shfl_xor_sync(~0u, y, 1);
        if (!half){
            float out = (ysum + uv*Dd) * siluf(zv);
            y2[base] = out;
        }
        base = baseN; xb = xbN;
        dv = dvN; uv = uvN; zv = zvN;
        B0 = B0N; B1 = B1N; C0 = C0N; C1 = C1N;
    }
}

// ---------------- head: partial GEMM per patch index p ----------------
__global__ void head_partial(const float* __restrict__ zf, const float* __restrict__ hw){
    int p = blockIdx.x, mt = blockIdx.y;     // p in [0,63), mt in [0,4)
    __shared__ float As[16][64];
    __shared__ float Ws[16][96];
    int tid = threadIdx.x;                   // 256
    int lm = tid >> 2, lk = (tid & 3) * 4;
    int bkrow = mt*64 + lm;
    int b = bkrow >> 4, kk = bkrow & 15;
    const float* Ag = zf + (size_t)(b*SEQ + p*KVAR + kk)*DM + lk;
    int tx = tid & 15, ty = tid >> 4;
    float acc[4][6];
#pragma unroll
    for (int i = 0; i < 4; i++)
#pragma unroll
        for (int j = 0; j < 6; j++) acc[i][j] = 0.f;

    for (int kt = 0; kt < DM; kt += 16){
        float4 av = *(const float4*)(Ag + kt);
        As[lk+0][lm]=av.x; As[lk+1][lm]=av.y; As[lk+2][lm]=av.z; As[lk+3][lm]=av.w;
#pragma unroll
        for (int i = 0; i < 6; i++){
            int e = tid + i*256;             // 1536 = 96*16 elements
            int n = e >> 4, kq = e & 15;
            Ws[kq][n] = hw[(size_t)n*HWLD + p*DM + kt + kq];
        }
        __syncthreads();
#pragma unroll
        for (int k = 0; k < 16; k++){
            float4 a = *(const float4*)&As[k][ty*4];
            float av4[4] = {a.x, a.y, a.z, a.w};
#pragma unroll
            for (int j = 0; j < 6; j++){
                float wv = Ws[k][tx*6 + j];
#pragma unroll
                for (int i = 0; i < 4; i++) acc[i][j] += av4[i]*wv;
            }
        }
        __syncthreads();
    }
#pragma unroll
    for (int i = 0; i < 4; i++)
#pragma unroll
        for (int j = 0; j < 6; j++)
            g_headp[(size_t)(p*256 + mt*64 + ty*4 + i)*HPRED + tx*6 + j] = acc[i][j];
}

// ---------------- head reduction + de-normalization ----------------
__global__ void head_final(const float* __restrict__ hb, float* __restrict__ out){
    int idx = blockIdx.x*256 + threadIdx.x;  // 24576 = 256*96
    int bk = idx / HPRED, hh = idx % HPRED;
    float s = 0.f;
    for (int p = 0; p < PP; p++) s += g_headp[(size_t)p*(BB*KVAR*HPRED) + idx];
    s += hb[hh];
    int b = bk >> 4, k = bk & 15;
    out[b*(HPRED*KVAR) + hh*KVAR + k] = s * g_std[bk] + g_mean[bk];
}

// ---------------- launch ----------------
extern "C" void kernel_launch(void* const* d_in, const int* in_sizes, int n_in,
                              void* d_out, int out_size){
    const float* x        = (const float*)d_in[0];
    const float* patch_w  = (const float*)d_in[1];
    const float* patch_b  = (const float*)d_in[2];
    const float* pos      = (const float*)d_in[3];
    const float* vemb     = (const float*)d_in[4];
    const float* in_w     = (const float*)d_in[5];
    const float* xp_w     = (const float*)d_in[6];
    const float* dt_w     = (const float*)d_in[7];
    const float* dt_b     = (const float*)d_in[8];
    const float* A_log    = (const float*)d_in[9];
    const float* D_par    = (const float*)d_in[10];
    const float* out_w    = (const float*)d_in[11];
    const float* tmb_g    = (const float*)d_in[12];
    const float* tmb_b    = (const float*)d_in[13];
    const float* ffn_g    = (const float*)d_in[14];
    const float* ffn_b    = (const float*)d_in[15];
    const float* ffn_w1   = (const float*)d_in[16];
    const float* ffn_b1   = (const float*)d_in[17];
    const float* ffn_w2   = (const float*)d_in[18];
    const float* ffn_b2   = (const float*)d_in[19];
    const float* norm_g   = (const float*)d_in[20];
    const float* norm_b   = (const float*)d_in[21];
    const float* head_w   = (const float*)d_in[22];
    const float* head_b   = (const float*)d_in[23];
    float* out = (float*)d_out;

    float *z, *tmp, *hln, *u, *zgp, *xdbl, *delta, *y2, *hff;
    cudaGetSymbolAddress((void**)&z,    g_z);
    cudaGetSymbolAddress((void**)&tmp,  g_tmp);
    cudaGetSymbolAddress((void**)&hln,  g_hln);
    cudaGetSymbolAddress((void**)&u,    g_u);
    cudaGetSymbolAddress((void**)&zgp,  g_zg);
    cudaGetSymbolAddress((void**)&xdbl, g_xdbl);
    cudaGetSymbolAddress((void**)&delta,g_delta);
    cudaGetSymbolAddress((void**)&y2,   g_y2);
    cudaGetSymbolAddress((void**)&hff,  g_hff);

    stats_kernel<<<BB*KVAR, 256>>>(x);
    embed_kernel<<<TT, 128>>>(x, patch_w, patch_b, pos, vemb);

    const int MT  = TT/128;   // 126 M tiles (128-row)
    const int MT64= TT/64;    // 252 M tiles (64-row)

    for (int l = 0; l < NLAY; l++){
        const float* Wi  = in_w  + (size_t)l*(2*DIN)*DM;
        const float* Wx  = xp_w  + (size_t)l*64*DIN;
        const float* Wdt = dt_w  + (size_t)l*DIN*RNK;
        const float* bdt = dt_b  + (size_t)l*DIN;
        const float* Al  = A_log + (size_t)l*DIN*NST;
        const float* Dl  = D_par + (size_t)l*DIN;
        const float* Wo  = out_w + (size_t)l*DM*DIN;
        const float* W1  = ffn_w1+ (size_t)l*DFF*DM;
        const float* B1  = ffn_b1+ (size_t)l*DFF;
        const float* W2  = ffn_w2+ (size_t)l*DM*DFF;
        const float* B2  = ffn_b2+ (size_t)l*DM;

        // in_proj -> silu(u), zg   (N=2048, K=512)
        gemm_tc<EP_SPLIT><<<dim3(16, MT), 256>>>(z, DM, Wi, DM, u, zgp, 0, nullptr, nullptr);
        // x_proj: xdbl = u @ Wx^T   (N=64, K=1024) — 64x64 tiles for grid occupancy
        gemm_tc64<EP_NONE><<<dim3(1, MT64), 128>>>(u, DIN, Wx, DIN, xdbl, nullptr, 64, nullptr, nullptr);
        // delta = softplus(dt @ Wdt^T + bdt)  (N=1024, K=32)
        gemm_tc<EP_SOFTPLUS><<<dim3(8, MT), 256>>>(xdbl, 64, Wdt, RNK, delta, nullptr, DIN, bdt, nullptr);
        // selective scan (fused +u*D, *silu(zg))
        scan_kernel<<<128, 256>>>(delta, u, zgp, xdbl, Al, Dl, y2);
        // out_proj + residual into tmp  (N=512, K=1024)
        gemm_tc<EP_RES><<<dim3(4, MT), 256>>>(y2, DIN, Wo, DIN, tmp, nullptr, DM, nullptr, z);
        // LN(tmp)->z ; LN(z)->hln (ffn pre-norm)
        ln_kernel<true><<<TT/8, 256>>>(tmp, tmb_g + l*DM, tmb_b + l*DM, z,
                                       ffn_g + l*DM, ffn_b + l*DM, hln);
        // FFN
        gemm_tc<EP_GELU><<<dim3(16, MT), 256>>>(hln, DM, W1, DM, hff, nullptr, DFF, B1, nullptr);
        gemm_tc<EP_BIAS_RES><<<dim3(4, MT), 256>>>(hff, DFF, W2, DFF, z, nullptr, DM, B2, z);
    }

    // final LN -> tmp
    ln_kernel<false><<<TT/8, 256>>>(z, norm_g, norm_b, tmp, nullptr, nullptr, nullptr);
    // head
    head_partial<<<dim3(PP, 4), 256>>>(tmp, head_w);
    head_final<<<96, 256>>>(head_b, out);
    (void)in_sizes; (void)n_in; (void)out_size;
}